// round 15
// baseline (speedup 1.0000x reference)
#include <cuda_runtime.h>
#include <cstdint>

// Problem constants
#define NROWS   24000          // BS*Q
#define NTGT    2400           // BS*NT
#define KCLS    256
#define R_TILE  30             // rows per block (15 row-pairs); grid.x = 800
#define TPT     5              // targets per thread (strided by BLOCK)
#define BLOCK   160            // 5 warps
#define TT      (BLOCK*TPT)    // 800 targets per block-group
#define NGROUPS 3              // 3 * 800 = 2400 exactly -> zero lane waste

// ---------------------------------------------------------------------------
// Single fused kernel. Block = 30 rows x 800 targets (strided TPT=5).
//
// Prologue computes the focal class-cost diff (pos - neg + 2) for its 30 rows
// directly from logits into smem (no global scratch, no separate kernel),
// stored ROW-PAIR INTERLEAVED: sdiff[(row/2)*512 + col*2 + (row&1)], so the
// main loop's class gather is one LDS.64 serving BOTH rows of a pair.
//
// GIoU via the half-width symmetric-interval identity:
//   mx      = max(|dcx|, |dw2|)
//   inter_w = (rw2+tw2) - mx   (SAT clamp: extents always in (0,1))
//   encl_w  = (rw2+tw2) + mx
// ---------------------------------------------------------------------------
__global__ __launch_bounds__(BLOCK) void k_main(const float* __restrict__ logits,
                                                const float* __restrict__ pboxes,
                                                const float* __restrict__ tboxes,
                                                const int* __restrict__ tids,
                                                float* __restrict__ out) {
    __shared__ __align__(16) float  sdiff[R_TILE * KCLS];  // 30 KB, pair-interleaved
    __shared__ __align__(16) float4 sbox[R_TILE];          // {cx, cy, 0.5w, 0.5h}
    __shared__ float  sarea[R_TILE];

    const int tid   = threadIdx.x;
    const int r0    = blockIdx.x * R_TILE;
    const int tbase = blockIdx.y * TT + tid;   // thread's first target; stride BLOCK

    // ---- Prologue A: row boxes ----
    if (tid < R_TILE) {
        float4 b = ((const float4*)pboxes)[r0 + tid];
        sarea[tid] = b.z * b.w;
        sbox[tid]  = make_float4(b.x, b.y, 0.5f * b.z, 0.5f * b.w);
    }

    // ---- Prologue B: fused focal diff compute (replaces k_diff + g_diff) ----
    // 30*256 = 7680 elems = 1920 float4; 12 float4 per thread, coalesced.
    {
        const float4* lg4 = (const float4*)(logits + (size_t)r0 * KCLS);
        #pragma unroll
        for (int i = 0; i < (R_TILE * KCLS / 4) / BLOCK; i++) {
            int e4  = tid + i * BLOCK;          // float4 index
            int row = (e4 * 4) >> 8;            // 64 float4 per row
            int col = (e4 * 4) & 255;
            float4 x4 = lg4[e4];
            float xs[4] = {x4.x, x4.y, x4.z, x4.w};
            // destination base for this group of 4 cols (same row)
            float* dst = sdiff + ((row >> 1) << 9) + (row & 1);
            #pragma unroll
            for (int k = 0; k < 4; k++) {
                float x = xs[k];
                float e = __expf(-x);
                float a = 1.0f + e;
                float s = __logf(a);            // = -ln(p) = softplus(-x)
                float p;
                asm("rcp.approx.f32 %0, %1;" : "=f"(p) : "f"(a));   // sigmoid
                float omp = 1.0f - p;
                float pos = (omp * omp) * (0.25f * s);
                float neg = (p * p) * (0.75f * (x + s));
                dst[(col + k) << 1] = (pos - neg) + 2.0f;   // fold GIoU "+2"
            }
        }
    }

    // ---- Prologue C: target data -> registers ----
    float tcx[TPT], tcy[TPT], tw2[TPT], th2[TPT], tarea[TPT];
    int   cof[TPT];   // pre-scaled: 2 * class_id (interleaved-layout offset)
    #pragma unroll
    for (int j = 0; j < TPT; j++) {
        int t = tbase + j * BLOCK;
        float4 b = ((const float4*)tboxes)[t];
        tcx[j] = b.x; tcy[j] = b.y;
        tw2[j] = 0.5f * b.z; th2[j] = 0.5f * b.w;
        tarea[j] = b.z * b.w;
        cof[j] = tids[t] << 1;
    }
    __syncthreads();

    float* op = out + (size_t)r0 * NTGT + tbase;

    // ---- Main loop over 15 row pairs ----
    #pragma unroll 1
    for (int rp = 0; rp < R_TILE / 2; rp++) {
        const float4 raA = sbox[2 * rp];
        const float4 raB = sbox[2 * rp + 1];
        const float  arA = sarea[2 * rp];
        const float  arB = sarea[2 * rp + 1];
        const float* dp  = sdiff + (rp << 9);   // row-pair base
        #pragma unroll
        for (int j = 0; j < TPT; j++) {
            float2 d2 = *(const float2*)(dp + cof[j]);   // {diff_rowA, diff_rowB}
            // ---------- row A ----------
            {
                float adx  = fabsf(raA.x - tcx[j]);
                float ady  = fabsf(raA.y - tcy[j]);
                float adwh = fabsf(raA.z - tw2[j]);
                float adhh = fabsf(raA.w - th2[j]);
                float bb = __fmaf_rn(2.0f, adwh + adhh, adx + ady);
                float sw2 = raA.z + tw2[j];
                float sh2 = raA.w + th2[j];
                float mxx = fmaxf(adx, adwh);
                float mxy = fmaxf(ady, adhh);
                float iw = __saturatef(sw2 - mxx);
                float ih = __saturatef(sh2 - mxy);
                float ew = sw2 + mxx;
                float eh = sh2 + mxy;
                float inter = iw * ih;
                float uni   = (arA + tarea[j]) - inter;
                float ea    = ew * eh;
                float ru, re;
                asm("rcp.approx.f32 %0, %1;" : "=f"(ru) : "f"(uni));
                asm("rcp.approx.f32 %0, %1;" : "=f"(re) : "f"(ea));
                float t1 = __fmaf_rn(inter, ru, uni * re);
                float c  = __fmaf_rn(5.0f, bb, d2.x);
                op[j * BLOCK] = __fmaf_rn(-2.0f, t1, c);
            }
            // ---------- row B ----------
            {
                float adx  = fabsf(raB.x - tcx[j]);
                float ady  = fabsf(raB.y - tcy[j]);
                float adwh = fabsf(raB.z - tw2[j]);
                float adhh = fabsf(raB.w - th2[j]);
                float bb = __fmaf_rn(2.0f, adwh + adhh, adx + ady);
                float sw2 = raB.z + tw2[j];
                float sh2 = raB.w + th2[j];
                float mxx = fmaxf(adx, adwh);
                float mxy = fmaxf(ady, adhh);
                float iw = __saturatef(sw2 - mxx);
                float ih = __saturatef(sh2 - mxy);
                float ew = sw2 + mxx;
                float eh = sh2 + mxy;
                float inter = iw * ih;
                float uni   = (arB + tarea[j]) - inter;
                float ea    = ew * eh;
                float ru, re;
                asm("rcp.approx.f32 %0, %1;" : "=f"(ru) : "f"(uni));
                asm("rcp.approx.f32 %0, %1;" : "=f"(re) : "f"(ea));
                float t1 = __fmaf_rn(inter, ru, uni * re);
                float c  = __fmaf_rn(5.0f, bb, d2.y);
                op[NTGT + j * BLOCK] = __fmaf_rn(-2.0f, t1, c);
            }
        }
        op += 2 * NTGT;
    }
}

// ---------------------------------------------------------------------------
extern "C" void kernel_launch(void* const* d_in, const int* in_sizes, int n_in,
                              void* d_out, int out_size) {
    const float* logits = (const float*)d_in[0];   // [16,1500,256]
    const float* pboxes = (const float*)d_in[1];   // [24000,4]
    const float* tboxes = (const float*)d_in[2];   // [2400,4]
    const int*   tids   = (const int*)  d_in[3];   // [2400]
    float* out = (float*)d_out;

    dim3 grid(NROWS / R_TILE, NGROUPS);
    k_main<<<grid, BLOCK>>>(logits, pboxes, tboxes, tids, out);
}